// round 14
// baseline (speedup 1.0000x reference)
#include <cuda_runtime.h>
#include <cuda_bf16.h>
#include <cstdint>

#define NN   50000
#define EE   800000
#define EHALF (EE / 2)          // edge pairs
#define PH   240000             // pairs handled on s2 arm (60%)
#define ETOT (EE + NN)
#define F1   256
#define HEADS 8
#define FULLMASK 0xffffffffu
#define SCAN_BLOCKS ((NN + 255) / 256)

// ---------------- device scratch ----------------
__device__ __nv_bfloat162 g_h1b[NN * (F1 / 2)];  // bf16 projection
__device__ float  g_as1[NN * HEADS];             // natural layout [n*8 + h]
__device__ float  g_ad1[NN * HEADS];
__device__ float4 g_node2[NN];
__device__ int    g_counts[NN];                  // zero-based degree; self-cleaned by scan1
__device__ int    g_off[NN + 1];
__device__ int    g_rank[EE];                    // per-edge rank within its dst (from hist)
__device__ int    g_csr[ETOT];
__device__ int    g_bsum[SCAN_BLOCKS];

__device__ __forceinline__ int warp_incl_scan(int x, int lane) {
    #pragma unroll
    for (int o = 1; o < 32; o <<= 1) {
        int n = __shfl_up_sync(FULLMASK, x, o);
        if (lane >= o) x += n;
    }
    return x;
}

// per-block dtype self-detection: sample first 256 entries as int64.
__device__ __forceinline__ int block_detect_is32(const void* eiv) {
    long long v = ((const long long*)eiv)[threadIdx.x & 255];
    int bad = (v < 0 || v >= (long long)NN) ? 1 : 0;
    return __syncthreads_or(bad);
}

// ---------------- histogram (2 edges/thread) + record ranks ----------
__global__ void hist_kernel(const void* __restrict__ eiv) {
    int is32 = block_detect_is32(eiv);
    int i = blockIdx.x * blockDim.x + threadIdx.x;
    if (i >= EHALF) return;
    int d0, d1;
    if (is32) {
        int2 p = ((const int2*)((const int*)eiv + EE))[i];
        d0 = p.x; d1 = p.y;
    } else {
        longlong2 p = ((const longlong2*)((const long long*)eiv + EE))[i];
        d0 = (int)p.x; d1 = (int)p.y;
    }
    int r0 = atomicAdd(&g_counts[d0], 1);
    int r1 = atomicAdd(&g_counts[d1], 1);
    g_rank[2 * i]     = r0;
    g_rank[2 * i + 1] = r1;
}

// ---------------- two-pass scan (proven): stage 1 ----------------
__global__ void scan1_kernel() {
    __shared__ int sw[8];
    int tid = threadIdx.x, lane = tid & 31, wid = tid >> 5;
    int idx = blockIdx.x * 256 + tid;
    int v = 0;
    if (idx < NN) {
        v = g_counts[idx] + 1;        // +1 = self loop
        g_counts[idx] = 0;            // self-clean for next call
    }
    int x = warp_incl_scan(v, lane);
    if (lane == 31) sw[wid] = x;
    __syncthreads();
    if (wid == 0) {
        int y = (lane < 8) ? sw[lane] : 0;
        #pragma unroll
        for (int o = 1; o < 8; o <<= 1) {
            int n = __shfl_up_sync(FULLMASK, y, o);
            if (lane >= o) y += n;
        }
        if (lane < 8) sw[lane] = y;
    }
    __syncthreads();
    int pre = wid ? sw[wid - 1] : 0;
    if (idx < NN) g_off[idx] = pre + x - v;
    if (tid == 255) g_bsum[blockIdx.x] = pre + x;
}

// stage 2: per-block reduction of preceding block sums + add
__global__ void scan3_kernel() {
    __shared__ int swr[8];
    __shared__ int stot;
    int tid = threadIdx.x, lane = tid & 31, wid = tid >> 5;
    int b = blockIdx.x;
    int v = (tid < b) ? g_bsum[tid] : 0;   // b < 256
    #pragma unroll
    for (int o = 16; o >= 1; o >>= 1) v += __shfl_xor_sync(FULLMASK, v, o);
    if (lane == 0) swr[wid] = v;
    __syncthreads();
    if (tid == 0) {
        int t = 0;
        #pragma unroll
        for (int j = 0; j < 8; j++) t += swr[j];
        stot = t;
    }
    __syncthreads();
    int idx = b * 256 + tid;
    if (idx < NN) g_off[idx] += stot;
    if (idx == 0) g_off[NN] = ETOT;
}

// ---------------- scatter A: pairs [0, PH) + self loops (s2 arm) -----------------
__global__ void scatterA_kernel(const void* __restrict__ eiv) {
    int is32 = block_detect_is32(eiv);
    int i = blockIdx.x * blockDim.x + threadIdx.x;
    if (i < PH) {
        int s0, s1, d0, d1;
        if (is32) {
            int2 ps = ((const int2*)eiv)[i];
            int2 pd = ((const int2*)((const int*)eiv + EE))[i];
            s0 = ps.x; s1 = ps.y; d0 = pd.x; d1 = pd.y;
        } else {
            longlong2 ps = ((const longlong2*)eiv)[i];
            longlong2 pd = ((const longlong2*)((const long long*)eiv + EE))[i];
            s0 = (int)ps.x; s1 = (int)ps.y; d0 = (int)pd.x; d1 = (int)pd.y;
        }
        g_csr[g_off[d0] + g_rank[2 * i]]     = s0;
        g_csr[g_off[d1] + g_rank[2 * i + 1]] = s1;
    } else if (i < PH + NN) {
        int n = i - PH;
        g_csr[g_off[n + 1] - 1] = n;   // self loop in the last slot
    }
}

// ---------------- scatter B: pairs [PH, EHALF) (main arm, after gemm1) -----------
__global__ void scatterB_kernel(const void* __restrict__ eiv) {
    int is32 = block_detect_is32(eiv);
    int i = PH + blockIdx.x * blockDim.x + threadIdx.x;
    if (i < EHALF) {
        int s0, s1, d0, d1;
        if (is32) {
            int2 ps = ((const int2*)eiv)[i];
            int2 pd = ((const int2*)((const int*)eiv + EE))[i];
            s0 = ps.x; s1 = ps.y; d0 = pd.x; d1 = pd.y;
        } else {
            longlong2 ps = ((const longlong2*)eiv)[i];
            longlong2 pd = ((const longlong2*)((const long long*)eiv + EE))[i];
            s0 = (int)ps.x; s1 = (int)ps.y; d0 = (int)pd.x; d1 = (int)pd.y;
        }
        g_csr[g_off[d0] + g_rank[2 * i]]     = s0;
        g_csr[g_off[d1] + g_rank[2 * i + 1]] = s1;
    }
}

// ---------------- cp.async helpers ----------------
__device__ __forceinline__ unsigned smem_u32(const void* p) {
    return (unsigned)__cvta_generic_to_shared(p);
}
__device__ __forceinline__ void cp16(unsigned dst, const void* src, bool pred) {
    int sz = pred ? 16 : 0;
    asm volatile("cp.async.cg.shared.global [%0], [%1], 16, %2;\n"
                 :: "r"(dst), "l"(src), "r"(sz));
}
__device__ __forceinline__ void cp_commit() {
    asm volatile("cp.async.commit_group;\n" ::: "memory");
}
template <int N>
__device__ __forceinline__ void cp_wait() {
    asm volatile("cp.async.wait_group %0;\n" :: "n"(N) : "memory");
}

// ---------------- layer1: tf32 GEMM (cp.async double-buffered, raw fp32-as-tf32),
//                  fused attention dots, bf16 output ----------
#define XS_STRIDE 20     // 16 K-words + 4 pad
#define WS_STRIDE 264    // 256 + 8 pad
#define KC 16            // K per chunk, 8 chunks
__global__ void __launch_bounds__(256) gemm1_kernel(const float* __restrict__ x,
                                                    const float* __restrict__ W,
                                                    const float* __restrict__ asrc,
                                                    const float* __restrict__ adst) {
    __shared__ unsigned xs[2][64 * XS_STRIDE];
    __shared__ unsigned ws[2][KC * WS_STRIDE];
    int tid = threadIdx.x;
    int lane = tid & 31, wid = tid >> 5;
    int wm = wid >> 2, wn = wid & 3;
    int g = lane >> 2, tig = lane & 3;
    int row0 = blockIdx.x * 64;

    int xr = tid >> 2, xg = tid & 3;
    bool xin = (row0 + xr) < NN;

    {
        cp16(smem_u32(&xs[0][xr * XS_STRIDE + xg * 4]),
             x + (long)(row0 + xr) * 128 + xg * 4, xin);
        #pragma unroll
        for (int i = 0; i < 4; i++) {
            int idx = tid + i * 256;
            int r = idx >> 6, grp = idx & 63;
            cp16(smem_u32(&ws[0][r * WS_STRIDE + grp * 4]),
                 W + (long)r * 256 + grp * 4, true);
        }
    }
    cp_commit();

    float acc[2][8][4];
    #pragma unroll
    for (int mi = 0; mi < 2; mi++)
        #pragma unroll
        for (int ni = 0; ni < 8; ni++)
            #pragma unroll
            for (int q = 0; q < 4; q++) acc[mi][ni][q] = 0.f;

    for (int c = 0; c < 8; c++) {
        int buf = c & 1;
        if (c < 7) {
            int nb = buf ^ 1;
            cp16(smem_u32(&xs[nb][xr * XS_STRIDE + xg * 4]),
                 x + (long)(row0 + xr) * 128 + (c + 1) * KC + xg * 4, xin);
            #pragma unroll
            for (int i = 0; i < 4; i++) {
                int idx = tid + i * 256;
                int r = idx >> 6, grp = idx & 63;
                cp16(smem_u32(&ws[nb][r * WS_STRIDE + grp * 4]),
                     W + (long)((c + 1) * KC + r) * 256 + grp * 4, true);
            }
            cp_commit();
            cp_wait<1>();
        } else {
            cp_wait<0>();
        }
        __syncthreads();

        #pragma unroll
        for (int kk = 0; kk < KC; kk += 8) {
            unsigned a[2][4];
            #pragma unroll
            for (int mi = 0; mi < 2; mi++) {
                int rb = wm * 32 + mi * 16;
                a[mi][0] = xs[buf][(rb + g) * XS_STRIDE + kk + tig];
                a[mi][1] = xs[buf][(rb + g + 8) * XS_STRIDE + kk + tig];
                a[mi][2] = xs[buf][(rb + g) * XS_STRIDE + kk + tig + 4];
                a[mi][3] = xs[buf][(rb + g + 8) * XS_STRIDE + kk + tig + 4];
            }
            #pragma unroll
            for (int ni = 0; ni < 8; ni++) {
                int cb = wn * 64 + ni * 8 + g;
                unsigned b0 = ws[buf][(kk + tig) * WS_STRIDE + cb];
                unsigned b1 = ws[buf][(kk + tig + 4) * WS_STRIDE + cb];
                #pragma unroll
                for (int mi = 0; mi < 2; mi++) {
                    asm volatile(
                        "mma.sync.aligned.m16n8k8.row.col.f32.tf32.tf32.f32 "
                        "{%0,%1,%2,%3}, {%4,%5,%6,%7}, {%8,%9}, {%0,%1,%2,%3};"
                        : "+f"(acc[mi][ni][0]), "+f"(acc[mi][ni][1]),
                          "+f"(acc[mi][ni][2]), "+f"(acc[mi][ni][3])
                        : "r"(a[mi][0]), "r"(a[mi][1]), "r"(a[mi][2]), "r"(a[mi][3]),
                          "r"(b0), "r"(b1));
                }
            }
        }
        __syncthreads();
    }

    // ---- fused epilogue: bf16 store + attention partial dots ----
    float pr[2][2][2][2];
    #pragma unroll
    for (int a0 = 0; a0 < 2; a0++)
        #pragma unroll
        for (int a1 = 0; a1 < 2; a1++)
            #pragma unroll
            for (int a2 = 0; a2 < 2; a2++)
                #pragma unroll
                for (int a3 = 0; a3 < 2; a3++) pr[a0][a1][a2][a3] = 0.f;

    #pragma unroll
    for (int ni = 0; ni < 8; ni++) {
        int c = wn * 64 + ni * 8 + tig * 2;
        float av0 = asrc[c], av1 = asrc[c + 1];
        float dv0 = adst[c], dv1 = adst[c + 1];
        int hi = ni >> 2;
        #pragma unroll
        for (int mi = 0; mi < 2; mi++) {
            pr[mi][0][hi][0] += acc[mi][ni][0] * av0 + acc[mi][ni][1] * av1;
            pr[mi][0][hi][1] += acc[mi][ni][0] * dv0 + acc[mi][ni][1] * dv1;
            pr[mi][1][hi][0] += acc[mi][ni][2] * av0 + acc[mi][ni][3] * av1;
            pr[mi][1][hi][1] += acc[mi][ni][2] * dv0 + acc[mi][ni][3] * dv1;

            int r0 = row0 + wm * 32 + mi * 16 + g;
            if (r0 < NN)
                g_h1b[r0 * 128 + (c >> 1)] =
                    __float22bfloat162_rn(make_float2(acc[mi][ni][0], acc[mi][ni][1]));
            int r1 = r0 + 8;
            if (r1 < NN)
                g_h1b[r1 * 128 + (c >> 1)] =
                    __float22bfloat162_rn(make_float2(acc[mi][ni][2], acc[mi][ni][3]));
        }
    }
    #pragma unroll
    for (int mi = 0; mi < 2; mi++)
        #pragma unroll
        for (int ab = 0; ab < 2; ab++)
            #pragma unroll
            for (int hi = 0; hi < 2; hi++)
                #pragma unroll
                for (int sd = 0; sd < 2; sd++) {
                    float v = pr[mi][ab][hi][sd];
                    v += __shfl_xor_sync(FULLMASK, v, 1);
                    v += __shfl_xor_sync(FULLMASK, v, 2);
                    pr[mi][ab][hi][sd] = v;
                }
    if (tig == 0) {
        #pragma unroll
        for (int mi = 0; mi < 2; mi++)
            #pragma unroll
            for (int ab = 0; ab < 2; ab++) {
                int r = row0 + wm * 32 + mi * 16 + ab * 8 + g;
                if (r < NN) {
                    #pragma unroll
                    for (int hi = 0; hi < 2; hi++) {
                        int h = 2 * wn + hi;
                        g_as1[r * 8 + h] = pr[mi][ab][hi][0];
                        g_ad1[r * 8 + h] = pr[mi][ab][hi][1];
                    }
                }
            }
    }
}

// ---------------- layer1 aggregation + softmax + ELU + fused proj2 ----------------
__global__ void __launch_bounds__(256) agg1_kernel(const float* __restrict__ b1,
                                                   const float* __restrict__ W2,
                                                   const float* __restrict__ as2,
                                                   const float* __restrict__ ad2v) {
    int w = (blockIdx.x * blockDim.x + threadIdx.x) >> 5;
    int lane = threadIdx.x & 31;
    if (w >= NN) return;
    int h = lane >> 2;
    float ad = g_ad1[w * 8 + h];
    int beg = g_off[w], end = g_off[w + 1];
    float acc[8];
    #pragma unroll
    for (int j = 0; j < 8; j++) acc[j] = 0.f;
    float den = 0.f;

    int e = beg;
    for (; e + 3 < end; e += 4) {
        int s0 = g_csr[e], s1 = g_csr[e + 1], s2 = g_csr[e + 2], s3 = g_csr[e + 3];
        float w0 = g_as1[s0 * 8 + h], w1 = g_as1[s1 * 8 + h];
        float w2 = g_as1[s2 * 8 + h], w3 = g_as1[s3 * 8 + h];
        uint4 u0 = ((const uint4*)(g_h1b + s0 * 128))[lane];
        uint4 u1 = ((const uint4*)(g_h1b + s1 * 128))[lane];
        uint4 u2 = ((const uint4*)(g_h1b + s2 * 128))[lane];
        uint4 u3 = ((const uint4*)(g_h1b + s3 * 128))[lane];

        float t0 = w0 + ad; t0 = t0 > 0.f ? t0 : 0.2f * t0;
        float t1 = w1 + ad; t1 = t1 > 0.f ? t1 : 0.2f * t1;
        float t2 = w2 + ad; t2 = t2 > 0.f ? t2 : 0.2f * t2;
        float t3 = w3 + ad; t3 = t3 > 0.f ? t3 : 0.2f * t3;
        float p0 = __expf(t0), p1 = __expf(t1), p2 = __expf(t2), p3 = __expf(t3);
        den += p0 + p1 + p2 + p3;

        #define ACC_ROW(u, p)                                              \
        {   float2 f0 = __bfloat1622float2(*(__nv_bfloat162*)&(u).x);      \
            float2 f1 = __bfloat1622float2(*(__nv_bfloat162*)&(u).y);      \
            float2 f2 = __bfloat1622float2(*(__nv_bfloat162*)&(u).z);      \
            float2 f3 = __bfloat1622float2(*(__nv_bfloat162*)&(u).w);      \
            acc[0] += (p) * f0.x; acc[1] += (p) * f0.y;                    \
            acc[2] += (p) * f1.x; acc[3] += (p) * f1.y;                    \
            acc[4] += (p) * f2.x; acc[5] += (p) * f2.y;                    \
            acc[6] += (p) * f3.x; acc[7] += (p) * f3.y; }
        ACC_ROW(u0, p0) ACC_ROW(u1, p1) ACC_ROW(u2, p2) ACC_ROW(u3, p3)
    }
    for (; e < end; e++) {
        int s = g_csr[e];
        float as = g_as1[s * 8 + h];
        uint4 u = ((const uint4*)(g_h1b + s * 128))[lane];
        float t = as + ad; t = t > 0.f ? t : 0.2f * t;
        float p = __expf(t);
        den += p;
        ACC_ROW(u, p)
    }
    #undef ACC_ROW

    float inv = 1.f / den;
    float4 bb0 = *(const float4*)&b1[lane * 8];
    float4 bb1 = *(const float4*)&b1[lane * 8 + 4];
    float o[8];
    o[0] = acc[0] * inv + bb0.x;  o[1] = acc[1] * inv + bb0.y;
    o[2] = acc[2] * inv + bb0.z;  o[3] = acc[3] * inv + bb0.w;
    o[4] = acc[4] * inv + bb1.x;  o[5] = acc[5] * inv + bb1.y;
    o[6] = acc[6] * inv + bb1.z;  o[7] = acc[7] * inv + bb1.w;
    #pragma unroll
    for (int j = 0; j < 8; j++)
        o[j] = o[j] > 0.f ? o[j] : expm1f(o[j]);

    const float4* w4 = (const float4*)(W2 + lane * 16);
    float4 q0 = w4[0], q1 = w4[1], q2 = w4[2], q3 = w4[3];
    float s0 = o[0]*q0.x + o[1]*q0.z + o[2]*q1.x + o[3]*q1.z
             + o[4]*q2.x + o[5]*q2.z + o[6]*q3.x + o[7]*q3.z;
    float s1 = o[0]*q0.y + o[1]*q0.w + o[2]*q1.y + o[3]*q1.w
             + o[4]*q2.y + o[5]*q2.w + o[6]*q3.y + o[7]*q3.w;
    #pragma unroll
    for (int off = 16; off >= 1; off >>= 1) {
        s0 += __shfl_xor_sync(FULLMASK, s0, off);
        s1 += __shfl_xor_sync(FULLMASK, s1, off);
    }
    if (lane == 0) {
        float a = s0 * as2[0] + s1 * as2[1];
        float d = s0 * ad2v[0] + s1 * ad2v[1];
        g_node2[w] = make_float4(s0, s1, a, d);
    }
}

// ---------------- layer 2 aggregation + log_softmax (half-warp per dst) ----------
__global__ void agg2_kernel(const float* __restrict__ b2, float* __restrict__ out) {
    int hw = (blockIdx.x * blockDim.x + threadIdx.x) >> 4;
    int l16 = threadIdx.x & 15;
    if (hw >= NN) return;
    float ad = g_node2[hw].w;
    int beg = g_off[hw], end = g_off[hw + 1];
    float sp = 0.f, s0 = 0.f, s1 = 0.f;
    for (int e = beg + l16; e < end; e += 16) {
        int s = g_csr[e];
        float4 v = g_node2[s];
        float t = v.z + ad;
        t = t > 0.f ? t : 0.2f * t;
        float p = __expf(t);
        sp += p; s0 += p * v.x; s1 += p * v.y;
    }
    #pragma unroll
    for (int o = 8; o >= 1; o >>= 1) {
        sp += __shfl_xor_sync(FULLMASK, sp, o);
        s0 += __shfl_xor_sync(FULLMASK, s0, o);
        s1 += __shfl_xor_sync(FULLMASK, s1, o);
    }
    if (l16 == 0) {
        float z0 = s0 / sp + b2[0];
        float z1 = s1 / sp + b2[1];
        float m = fmaxf(z0, z1);
        float l = m + logf(expf(z0 - m) + expf(z1 - m));
        out[hw * 2 + 0] = z0 - l;
        out[hw * 2 + 1] = z1 - l;
    }
}

// ---------------- launch: CSR chain || gemm1, scatter split across arms ----------
extern "C" void kernel_launch(void* const* d_in, const int* in_sizes, int n_in,
                              void* d_out, int out_size) {
    const float* x    = (const float*)d_in[0];
    const void*  ei   = d_in[1];
    const float* W1   = (const float*)d_in[2];
    const float* as1  = (const float*)d_in[3];
    const float* ad1  = (const float*)d_in[4];
    const float* b1   = (const float*)d_in[5];
    const float* W2   = (const float*)d_in[6];
    const float* as2  = (const float*)d_in[7];
    const float* ad2  = (const float*)d_in[8];
    const float* b2   = (const float*)d_in[9];
    float* out = (float*)d_out;

    static cudaStream_t s2 = nullptr;
    static cudaEvent_t evFork = nullptr, evCsr = nullptr, evJoin = nullptr;
    if (s2 == nullptr) {
        cudaStreamCreateWithFlags(&s2, cudaStreamNonBlocking);
        cudaEventCreateWithFlags(&evFork, cudaEventDisableTiming);
        cudaEventCreateWithFlags(&evCsr, cudaEventDisableTiming);
        cudaEventCreateWithFlags(&evJoin, cudaEventDisableTiming);
    }

    const int TB = 256;

    cudaEventRecord(evFork, 0);
    cudaStreamWaitEvent(s2, evFork, 0);

    // s2 arm: hist -> scans -> (publish offsets) -> scatterA (+self loops)
    hist_kernel<<<(EHALF + TB - 1) / TB, TB, 0, s2>>>(ei);
    scan1_kernel<<<SCAN_BLOCKS, 256, 0, s2>>>();
    scan3_kernel<<<SCAN_BLOCKS, 256, 0, s2>>>();
    cudaEventRecord(evCsr, s2);
    scatterA_kernel<<<(PH + NN + TB - 1) / TB, TB, 0, s2>>>(ei);
    cudaEventRecord(evJoin, s2);

    // main arm: gemm1, then the remaining 40% of scatter once offsets are ready
    gemm1_kernel<<<(NN + 63) / 64, 256>>>(x, W1, as1, ad1);
    cudaStreamWaitEvent(0, evCsr, 0);
    scatterB_kernel<<<(EHALF - PH + TB - 1) / TB, TB>>>(ei);

    // join: agg1 needs scatterA (s2) and scatterB (main)
    cudaStreamWaitEvent(0, evJoin, 0);

    int warpBlocks = (NN + 7) / 8;
    agg1_kernel<<<warpBlocks, TB>>>(b1, W2, as2, ad2);
    agg2_kernel<<<(NN * 16 + TB - 1) / TB, TB>>>(b2, out);
}

// round 15
// speedup vs baseline: 1.0358x; 1.0358x over previous
#include <cuda_runtime.h>
#include <cuda_bf16.h>
#include <cstdint>

#define NN   50000
#define EE   800000
#define EHALF (EE / 2)
#define ETOT (EE + NN)
#define F1   256
#define HEADS 8
#define FULLMASK 0xffffffffu
#define SCAN_BLOCKS ((NN + 255) / 256)

// ---------------- device scratch ----------------
__device__ __nv_bfloat162 g_h1b[NN * (F1 / 2)];  // bf16 projection
__device__ float  g_as1[NN * HEADS];             // natural layout [n*8 + h]
__device__ float  g_ad1[NN * HEADS];
__device__ float4 g_node2[NN];
__device__ int    g_counts[NN];                  // zero-based degree; self-cleaned by scan
__device__ int    g_off[NN + 1];
__device__ int    g_rank[EE];                    // per-edge rank within its dst (from hist)
__device__ int    g_csr[ETOT];
__device__ int    g_pub[SCAN_BLOCKS];            // scan publish slots (zeroed by hist)

__device__ __forceinline__ int warp_incl_scan(int x, int lane) {
    #pragma unroll
    for (int o = 1; o < 32; o <<= 1) {
        int n = __shfl_up_sync(FULLMASK, x, o);
        if (lane >= o) x += n;
    }
    return x;
}

// per-block dtype self-detection: sample first 256 entries as int64.
__device__ __forceinline__ int block_detect_is32(const void* eiv) {
    long long v = ((const long long*)eiv)[threadIdx.x & 255];
    int bad = (v < 0 || v >= (long long)NN) ? 1 : 0;
    return __syncthreads_or(bad);
}

// ---------------- histogram (2 edges/thread) + record ranks + zero g_pub ----------
__global__ void hist_kernel(const void* __restrict__ eiv) {
    int is32 = block_detect_is32(eiv);
    int i = blockIdx.x * blockDim.x + threadIdx.x;
    if (i < SCAN_BLOCKS) g_pub[i] = 0;
    if (i >= EHALF) return;
    int d0, d1;
    if (is32) {
        int2 p = ((const int2*)((const int*)eiv + EE))[i];
        d0 = p.x; d1 = p.y;
    } else {
        longlong2 p = ((const longlong2*)((const long long*)eiv + EE))[i];
        d0 = (int)p.x; d1 = (int)p.y;
    }
    int r0 = atomicAdd(&g_counts[d0], 1);
    int r1 = atomicAdd(&g_counts[d1], 1);
    g_rank[2 * i]     = r0;
    g_rank[2 * i + 1] = r1;
}

// ---------------- single-kernel scan: parallel publish + parallel poll -----------
// Block b publishes (total+1) to g_pub[b] (flag and value share one word, so no
// ordering hazard); thread tid<b polls g_pub[tid]; all blocks co-resident (196).
__global__ void scan_kernel() {
    __shared__ int sw[8];
    __shared__ int sbase;
    int tid = threadIdx.x, lane = tid & 31, wid = tid >> 5;
    int b = blockIdx.x;
    int idx = b * 256 + tid;
    int v = 0;
    if (idx < NN) {
        v = g_counts[idx] + 1;        // +1 = self loop
        g_counts[idx] = 0;            // self-clean for next call
    }
    int x = warp_incl_scan(v, lane);
    if (lane == 31) sw[wid] = x;
    __syncthreads();
    if (wid == 0) {
        int y = (lane < 8) ? sw[lane] : 0;
        #pragma unroll
        for (int o = 1; o < 8; o <<= 1) {
            int n = __shfl_up_sync(FULLMASK, y, o);
            if (lane >= o) y += n;
        }
        if (lane < 8) sw[lane] = y;
    }
    __syncthreads();
    int pre = wid ? sw[wid - 1] : 0;
    int excl = pre + x - v;
    int total = sw[7];

    if (tid == 0) atomicExch(&g_pub[b], total + 1);

    int part = 0;
    if (tid < b) {                     // b <= 195 < 256
        int pv;
        do { pv = atomicAdd(&g_pub[tid], 0); } while (pv == 0);
        part = pv - 1;
    }
    __syncthreads();                   // sw reuse barrier
    #pragma unroll
    for (int o = 16; o >= 1; o >>= 1) part += __shfl_xor_sync(FULLMASK, part, o);
    if (lane == 0) sw[wid] = part;
    __syncthreads();
    if (tid == 0) {
        int t = 0;
        #pragma unroll
        for (int j = 0; j < 8; j++) t += sw[j];
        sbase = t;
    }
    __syncthreads();
    if (idx < NN) g_off[idx] = sbase + excl;
    if (idx == 0) g_off[NN] = ETOT;
}

// ---------------- scatter: atomic-free, rank-based (2 edges/thread) --------------
__global__ void scatter_kernel(const void* __restrict__ eiv) {
    int is32 = block_detect_is32(eiv);
    int i = blockIdx.x * blockDim.x + threadIdx.x;
    if (i < EHALF) {
        int s0, s1, d0, d1;
        if (is32) {
            int2 ps = ((const int2*)eiv)[i];
            int2 pd = ((const int2*)((const int*)eiv + EE))[i];
            s0 = ps.x; s1 = ps.y; d0 = pd.x; d1 = pd.y;
        } else {
            longlong2 ps = ((const longlong2*)eiv)[i];
            longlong2 pd = ((const longlong2*)((const long long*)eiv + EE))[i];
            s0 = (int)ps.x; s1 = (int)ps.y; d0 = (int)pd.x; d1 = (int)pd.y;
        }
        g_csr[g_off[d0] + g_rank[2 * i]]     = s0;
        g_csr[g_off[d1] + g_rank[2 * i + 1]] = s1;
    } else if (i < EHALF + NN) {
        int n = i - EHALF;
        g_csr[g_off[n + 1] - 1] = n;   // self loop in the last slot
    }
}

// ---------------- cp.async helpers ----------------
__device__ __forceinline__ unsigned smem_u32(const void* p) {
    return (unsigned)__cvta_generic_to_shared(p);
}
__device__ __forceinline__ void cp16(unsigned dst, const void* src, bool pred) {
    int sz = pred ? 16 : 0;
    asm volatile("cp.async.cg.shared.global [%0], [%1], 16, %2;\n"
                 :: "r"(dst), "l"(src), "r"(sz));
}
__device__ __forceinline__ void cp_commit() {
    asm volatile("cp.async.commit_group;\n" ::: "memory");
}
template <int N>
__device__ __forceinline__ void cp_wait() {
    asm volatile("cp.async.wait_group %0;\n" :: "n"(N) : "memory");
}

// ---------------- layer1: tf32 GEMM (cp.async double-buffered, raw fp32-as-tf32),
//                  fused attention dots, bf16 output ----------
#define XS_STRIDE 20     // 16 K-words + 4 pad
#define WS_STRIDE 264    // 256 + 8 pad
#define KC 16            // K per chunk, 8 chunks
__global__ void __launch_bounds__(256) gemm1_kernel(const float* __restrict__ x,
                                                    const float* __restrict__ W,
                                                    const float* __restrict__ asrc,
                                                    const float* __restrict__ adst) {
    __shared__ unsigned xs[2][64 * XS_STRIDE];
    __shared__ unsigned ws[2][KC * WS_STRIDE];
    int tid = threadIdx.x;
    int lane = tid & 31, wid = tid >> 5;
    int wm = wid >> 2, wn = wid & 3;
    int g = lane >> 2, tig = lane & 3;
    int row0 = blockIdx.x * 64;

    int xr = tid >> 2, xg = tid & 3;
    bool xin = (row0 + xr) < NN;

    {
        cp16(smem_u32(&xs[0][xr * XS_STRIDE + xg * 4]),
             x + (long)(row0 + xr) * 128 + xg * 4, xin);
        #pragma unroll
        for (int i = 0; i < 4; i++) {
            int idx = tid + i * 256;
            int r = idx >> 6, grp = idx & 63;
            cp16(smem_u32(&ws[0][r * WS_STRIDE + grp * 4]),
                 W + (long)r * 256 + grp * 4, true);
        }
    }
    cp_commit();

    float acc[2][8][4];
    #pragma unroll
    for (int mi = 0; mi < 2; mi++)
        #pragma unroll
        for (int ni = 0; ni < 8; ni++)
            #pragma unroll
            for (int q = 0; q < 4; q++) acc[mi][ni][q] = 0.f;

    for (int c = 0; c < 8; c++) {
        int buf = c & 1;
        if (c < 7) {
            int nb = buf ^ 1;
            cp16(smem_u32(&xs[nb][xr * XS_STRIDE + xg * 4]),
                 x + (long)(row0 + xr) * 128 + (c + 1) * KC + xg * 4, xin);
            #pragma unroll
            for (int i = 0; i < 4; i++) {
                int idx = tid + i * 256;
                int r = idx >> 6, grp = idx & 63;
                cp16(smem_u32(&ws[nb][r * WS_STRIDE + grp * 4]),
                     W + (long)((c + 1) * KC + r) * 256 + grp * 4, true);
            }
            cp_commit();
            cp_wait<1>();
        } else {
            cp_wait<0>();
        }
        __syncthreads();

        #pragma unroll
        for (int kk = 0; kk < KC; kk += 8) {
            unsigned a[2][4];
            #pragma unroll
            for (int mi = 0; mi < 2; mi++) {
                int rb = wm * 32 + mi * 16;
                a[mi][0] = xs[buf][(rb + g) * XS_STRIDE + kk + tig];
                a[mi][1] = xs[buf][(rb + g + 8) * XS_STRIDE + kk + tig];
                a[mi][2] = xs[buf][(rb + g) * XS_STRIDE + kk + tig + 4];
                a[mi][3] = xs[buf][(rb + g + 8) * XS_STRIDE + kk + tig + 4];
            }
            #pragma unroll
            for (int ni = 0; ni < 8; ni++) {
                int cb = wn * 64 + ni * 8 + g;
                unsigned b0 = ws[buf][(kk + tig) * WS_STRIDE + cb];
                unsigned b1 = ws[buf][(kk + tig + 4) * WS_STRIDE + cb];
                #pragma unroll
                for (int mi = 0; mi < 2; mi++) {
                    asm volatile(
                        "mma.sync.aligned.m16n8k8.row.col.f32.tf32.tf32.f32 "
                        "{%0,%1,%2,%3}, {%4,%5,%6,%7}, {%8,%9}, {%0,%1,%2,%3};"
                        : "+f"(acc[mi][ni][0]), "+f"(acc[mi][ni][1]),
                          "+f"(acc[mi][ni][2]), "+f"(acc[mi][ni][3])
                        : "r"(a[mi][0]), "r"(a[mi][1]), "r"(a[mi][2]), "r"(a[mi][3]),
                          "r"(b0), "r"(b1));
                }
            }
        }
        __syncthreads();
    }

    // ---- fused epilogue: bf16 store + attention partial dots ----
    float pr[2][2][2][2];
    #pragma unroll
    for (int a0 = 0; a0 < 2; a0++)
        #pragma unroll
        for (int a1 = 0; a1 < 2; a1++)
            #pragma unroll
            for (int a2 = 0; a2 < 2; a2++)
                #pragma unroll
                for (int a3 = 0; a3 < 2; a3++) pr[a0][a1][a2][a3] = 0.f;

    #pragma unroll
    for (int ni = 0; ni < 8; ni++) {
        int c = wn * 64 + ni * 8 + tig * 2;
        float av0 = asrc[c], av1 = asrc[c + 1];
        float dv0 = adst[c], dv1 = adst[c + 1];
        int hi = ni >> 2;
        #pragma unroll
        for (int mi = 0; mi < 2; mi++) {
            pr[mi][0][hi][0] += acc[mi][ni][0] * av0 + acc[mi][ni][1] * av1;
            pr[mi][0][hi][1] += acc[mi][ni][0] * dv0 + acc[mi][ni][1] * dv1;
            pr[mi][1][hi][0] += acc[mi][ni][2] * av0 + acc[mi][ni][3] * av1;
            pr[mi][1][hi][1] += acc[mi][ni][2] * dv0 + acc[mi][ni][3] * dv1;

            int r0 = row0 + wm * 32 + mi * 16 + g;
            if (r0 < NN)
                g_h1b[r0 * 128 + (c >> 1)] =
                    __float22bfloat162_rn(make_float2(acc[mi][ni][0], acc[mi][ni][1]));
            int r1 = r0 + 8;
            if (r1 < NN)
                g_h1b[r1 * 128 + (c >> 1)] =
                    __float22bfloat162_rn(make_float2(acc[mi][ni][2], acc[mi][ni][3]));
        }
    }
    #pragma unroll
    for (int mi = 0; mi < 2; mi++)
        #pragma unroll
        for (int ab = 0; ab < 2; ab++)
            #pragma unroll
            for (int hi = 0; hi < 2; hi++)
                #pragma unroll
                for (int sd = 0; sd < 2; sd++) {
                    float v = pr[mi][ab][hi][sd];
                    v += __shfl_xor_sync(FULLMASK, v, 1);
                    v += __shfl_xor_sync(FULLMASK, v, 2);
                    pr[mi][ab][hi][sd] = v;
                }
    if (tig == 0) {
        #pragma unroll
        for (int mi = 0; mi < 2; mi++)
            #pragma unroll
            for (int ab = 0; ab < 2; ab++) {
                int r = row0 + wm * 32 + mi * 16 + ab * 8 + g;
                if (r < NN) {
                    #pragma unroll
                    for (int hi = 0; hi < 2; hi++) {
                        int h = 2 * wn + hi;
                        g_as1[r * 8 + h] = pr[mi][ab][hi][0];
                        g_ad1[r * 8 + h] = pr[mi][ab][hi][1];
                    }
                }
            }
    }
}

// ---------------- layer1 aggregation + softmax + ELU + fused proj2 ----------------
__global__ void __launch_bounds__(256) agg1_kernel(const float* __restrict__ b1,
                                                   const float* __restrict__ W2,
                                                   const float* __restrict__ as2,
                                                   const float* __restrict__ ad2v) {
    int w = (blockIdx.x * blockDim.x + threadIdx.x) >> 5;
    int lane = threadIdx.x & 31;
    if (w >= NN) return;
    int h = lane >> 2;
    float ad = g_ad1[w * 8 + h];
    int beg = g_off[w], end = g_off[w + 1];
    float acc[8];
    #pragma unroll
    for (int j = 0; j < 8; j++) acc[j] = 0.f;
    float den = 0.f;

    int e = beg;
    for (; e + 3 < end; e += 4) {
        int s0 = g_csr[e], s1 = g_csr[e + 1], s2 = g_csr[e + 2], s3 = g_csr[e + 3];
        float w0 = g_as1[s0 * 8 + h], w1 = g_as1[s1 * 8 + h];
        float w2 = g_as1[s2 * 8 + h], w3 = g_as1[s3 * 8 + h];
        uint4 u0 = ((const uint4*)(g_h1b + s0 * 128))[lane];
        uint4 u1 = ((const uint4*)(g_h1b + s1 * 128))[lane];
        uint4 u2 = ((const uint4*)(g_h1b + s2 * 128))[lane];
        uint4 u3 = ((const uint4*)(g_h1b + s3 * 128))[lane];

        float t0 = w0 + ad; t0 = t0 > 0.f ? t0 : 0.2f * t0;
        float t1 = w1 + ad; t1 = t1 > 0.f ? t1 : 0.2f * t1;
        float t2 = w2 + ad; t2 = t2 > 0.f ? t2 : 0.2f * t2;
        float t3 = w3 + ad; t3 = t3 > 0.f ? t3 : 0.2f * t3;
        float p0 = __expf(t0), p1 = __expf(t1), p2 = __expf(t2), p3 = __expf(t3);
        den += p0 + p1 + p2 + p3;

        #define ACC_ROW(u, p)                                              \
        {   float2 f0 = __bfloat1622float2(*(__nv_bfloat162*)&(u).x);      \
            float2 f1 = __bfloat1622float2(*(__nv_bfloat162*)&(u).y);      \
            float2 f2 = __bfloat1622float2(*(__nv_bfloat162*)&(u).z);      \
            float2 f3 = __bfloat1622float2(*(__nv_bfloat162*)&(u).w);      \
            acc[0] += (p) * f0.x; acc[1] += (p) * f0.y;                    \
            acc[2] += (p) * f1.x; acc[3] += (p) * f1.y;                    \
            acc[4] += (p) * f2.x; acc[5] += (p) * f2.y;                    \
            acc[6] += (p) * f3.x; acc[7] += (p) * f3.y; }
        ACC_ROW(u0, p0) ACC_ROW(u1, p1) ACC_ROW(u2, p2) ACC_ROW(u3, p3)
    }
    for (; e < end; e++) {
        int s = g_csr[e];
        float as = g_as1[s * 8 + h];
        uint4 u = ((const uint4*)(g_h1b + s * 128))[lane];
        float t = as + ad; t = t > 0.f ? t : 0.2f * t;
        float p = __expf(t);
        den += p;
        ACC_ROW(u, p)
    }
    #undef ACC_ROW

    float inv = 1.f / den;
    float4 bb0 = *(const float4*)&b1[lane * 8];
    float4 bb1 = *(const float4*)&b1[lane * 8 + 4];
    float o[8];
    o[0] = acc[0] * inv + bb0.x;  o[1] = acc[1] * inv + bb0.y;
    o[2] = acc[2] * inv + bb0.z;  o[3] = acc[3] * inv + bb0.w;
    o[4] = acc[4] * inv + bb1.x;  o[5] = acc[5] * inv + bb1.y;
    o[6] = acc[6] * inv + bb1.z;  o[7] = acc[7] * inv + bb1.w;
    #pragma unroll
    for (int j = 0; j < 8; j++)
        o[j] = o[j] > 0.f ? o[j] : expm1f(o[j]);

    const float4* w4 = (const float4*)(W2 + lane * 16);
    float4 q0 = w4[0], q1 = w4[1], q2 = w4[2], q3 = w4[3];
    float s0 = o[0]*q0.x + o[1]*q0.z + o[2]*q1.x + o[3]*q1.z
             + o[4]*q2.x + o[5]*q2.z + o[6]*q3.x + o[7]*q3.z;
    float s1 = o[0]*q0.y + o[1]*q0.w + o[2]*q1.y + o[3]*q1.w
             + o[4]*q2.y + o[5]*q2.w + o[6]*q3.y + o[7]*q3.w;
    #pragma unroll
    for (int off = 16; off >= 1; off >>= 1) {
        s0 += __shfl_xor_sync(FULLMASK, s0, off);
        s1 += __shfl_xor_sync(FULLMASK, s1, off);
    }
    if (lane == 0) {
        float a = s0 * as2[0] + s1 * as2[1];
        float d = s0 * ad2v[0] + s1 * ad2v[1];
        g_node2[w] = make_float4(s0, s1, a, d);
    }
}

// ---------------- layer 2 aggregation + log_softmax (half-warp per dst) ----------
__global__ void agg2_kernel(const float* __restrict__ b2, float* __restrict__ out) {
    int hw = (blockIdx.x * blockDim.x + threadIdx.x) >> 4;
    int l16 = threadIdx.x & 15;
    if (hw >= NN) return;
    float ad = g_node2[hw].w;
    int beg = g_off[hw], end = g_off[hw + 1];
    float sp = 0.f, s0 = 0.f, s1 = 0.f;
    for (int e = beg + l16; e < end; e += 16) {
        int s = g_csr[e];
        float4 v = g_node2[s];
        float t = v.z + ad;
        t = t > 0.f ? t : 0.2f * t;
        float p = __expf(t);
        sp += p; s0 += p * v.x; s1 += p * v.y;
    }
    #pragma unroll
    for (int o = 8; o >= 1; o >>= 1) {
        sp += __shfl_xor_sync(FULLMASK, sp, o);
        s0 += __shfl_xor_sync(FULLMASK, s0, o);
        s1 += __shfl_xor_sync(FULLMASK, s1, o);
    }
    if (l16 == 0) {
        float z0 = s0 / sp + b2[0];
        float z1 = s1 / sp + b2[1];
        float m = fmaxf(z0, z1);
        float l = m + logf(expf(z0 - m) + expf(z1 - m));
        out[hw * 2 + 0] = z0 - l;
        out[hw * 2 + 1] = z1 - l;
    }
}

// ---------------- launch: CSR chain || gemm1, fork-join via events ----------------
extern "C" void kernel_launch(void* const* d_in, const int* in_sizes, int n_in,
                              void* d_out, int out_size) {
    const float* x    = (const float*)d_in[0];
    const void*  ei   = d_in[1];
    const float* W1   = (const float*)d_in[2];
    const float* as1  = (const float*)d_in[3];
    const float* ad1  = (const float*)d_in[4];
    const float* b1   = (const float*)d_in[5];
    const float* W2   = (const float*)d_in[6];
    const float* as2  = (const float*)d_in[7];
    const float* ad2  = (const float*)d_in[8];
    const float* b2   = (const float*)d_in[9];
    float* out = (float*)d_out;

    static cudaStream_t s2 = nullptr;
    static cudaEvent_t evFork = nullptr, evJoin = nullptr;
    if (s2 == nullptr) {
        cudaStreamCreateWithFlags(&s2, cudaStreamNonBlocking);
        cudaEventCreateWithFlags(&evFork, cudaEventDisableTiming);
        cudaEventCreateWithFlags(&evJoin, cudaEventDisableTiming);
    }

    const int TB = 256;

    cudaEventRecord(evFork, 0);
    cudaStreamWaitEvent(s2, evFork, 0);

    hist_kernel<<<(EHALF + TB - 1) / TB, TB, 0, s2>>>(ei);
    scan_kernel<<<SCAN_BLOCKS, 256, 0, s2>>>();
    scatter_kernel<<<(EHALF + NN + TB - 1) / TB, TB, 0, s2>>>(ei);

    gemm1_kernel<<<(NN + 63) / 64, 256>>>(x, W1, as1, ad1);

    cudaEventRecord(evJoin, s2);
    cudaStreamWaitEvent(0, evJoin, 0);

    int warpBlocks = (NN + 7) / 8;
    agg1_kernel<<<warpBlocks, TB>>>(b1, W2, as2, ad2);
    agg2_kernel<<<(NN * 16 + TB - 1) / TB, TB>>>(b2, out);
}